// round 17
// baseline (speedup 1.0000x reference)
#include <cuda_runtime.h>
#include <cuda_fp16.h>
#include <cstdint>

#define SEQ     8
#define HDIM    512
#define HOUT    256
#define LN_EPS  1e-5f
#define MAX_ROWS 65536

// Scratch: fused (node + pooled) vectors, [N, 512], fp16.
__device__ __half g_fused[(size_t)MAX_ROWS * HDIM];
// Transposed + fp16-rounded out_W: [256, 512] (n-major, k-contiguous).
__device__ __half g_Bt[(size_t)HOUT * HDIM];

// ---------------------------------------------------------------------------
// Helpers
// ---------------------------------------------------------------------------
__device__ __forceinline__ uint32_t smem_u32(const void* p) {
    uint32_t a;
    asm("{ .reg .u64 t; cvta.to.shared.u64 t, %1; cvt.u32.u64 %0, t; }" : "=r"(a) : "l"(p));
    return a;
}

__device__ __forceinline__ void mma_fp16(float* d, const uint32_t* a, const uint32_t* b) {
    asm volatile(
        "mma.sync.aligned.m16n8k16.row.col.f32.f16.f16.f32 "
        "{%0,%1,%2,%3}, {%4,%5,%6,%7}, {%8,%9}, {%0,%1,%2,%3};"
        : "+f"(d[0]), "+f"(d[1]), "+f"(d[2]), "+f"(d[3])
        : "r"(a[0]), "r"(a[1]), "r"(a[2]), "r"(a[3]), "r"(b[0]), "r"(b[1]));
}

__device__ __forceinline__ void cp_async16(uint32_t dst, const void* src) {
    asm volatile("cp.async.cg.shared.global [%0], [%1], 16;"
                 :: "r"(dst), "l"(src) : "memory");
}
#define CP_COMMIT() asm volatile("cp.async.commit_group;" ::: "memory")
#define CP_WAIT(n)  asm volatile("cp.async.wait_group %0;" :: "n"(n) : "memory")

// ---------------------------------------------------------------------------
// Kernel A (v7): LayerNorm + attention pooling, software-pipelined row pair.
// CTA = 256 threads, thread owns 2 columns. Rows 2b, 2b+1 processed
// sequentially; row-1's loads are issued before row-0's reduction so they
// stay in flight through the compute phase (raises DRAM duty cycle).
// Math identical to the proven v4/v6 kernels.
// ---------------------------------------------------------------------------
__global__ __launch_bounds__(256) void ln_attn_v7_kernel(
    const float* __restrict__ x,
    const float* __restrict__ gamma,
    const float* __restrict__ beta,
    const float* __restrict__ attnW)
{
    __shared__ float s_red[8][26];
    __shared__ float s_k[2][8];
    __shared__ float s_K[2];

    const int tid  = threadIdx.x;
    const int w    = tid >> 5;
    const int lane = tid & 31;
    const size_t row0 = (size_t)blockIdx.x * 2;
    const int col = tid * 2;

    const float2* xr0 = reinterpret_cast<const float2*>(x + row0 * SEQ * HDIM);
    const float2* xr1 = reinterpret_cast<const float2*>(x + (row0 + 1) * SEQ * HDIM);
    const float2 gv = *reinterpret_cast<const float2*>(gamma + col);
    const float2 wn = *reinterpret_cast<const float2*>(attnW + HDIM + col);
    const float2 gw = make_float2(gv.x * wn.x, gv.y * wn.y);
    const float s1_local = gw.x + gw.y;

    // ---- row 0 loads + partials --------------------------------------------
    float2 xv0[SEQ];
    #pragma unroll
    for (int t = 0; t < SEQ; t++) xv0[t] = xr0[t * (HDIM / 2) + tid];

    float vals[32];
    #pragma unroll
    for (int t = 0; t < SEQ; t++) {
        const float2 v = xv0[t];
        vals[t]      = v.x + v.y;
        vals[8 + t]  = v.x * v.x + v.y * v.y;
        vals[16 + t] = gw.x * v.x + gw.y * v.y;
    }
    vals[24] = s1_local;
    #pragma unroll
    for (int j = 25; j < 32; j++) vals[j] = 0.f;

    // ---- issue row-1 loads NOW: in flight during row-0 reduce/softmax ------
    float2 xv1[SEQ];
    #pragma unroll
    for (int t = 0; t < SEQ; t++) xv1[t] = xr1[t * (HDIM / 2) + tid];

    // ---- row 0 reduce-scatter ----------------------------------------------
    #pragma unroll
    for (int bit = 16; bit >= 1; bit >>= 1) {
        #pragma unroll
        for (int j = 0; j < bit; j++) {
            const bool hi = (lane & bit) != 0;
            const float keep = hi ? vals[j + bit] : vals[j];
            const float send = hi ? vals[j] : vals[j + bit];
            vals[j] = keep + __shfl_xor_sync(0xffffffffu, send, bit);
        }
    }
    if (lane < 25) s_red[w][lane] = vals[0];
    __syncthreads();

    // ---- row 0 softmax (warp 0) --------------------------------------------
    if (w == 0) {
        float v = 0.f;
        if (lane < 25) {
            #pragma unroll
            for (int wi = 0; wi < 8; wi++) v += s_red[wi][lane];
        }
        const int t = lane & 7;
        const float S  = __shfl_sync(0xffffffffu, v, t);
        const float Q  = __shfl_sync(0xffffffffu, v, 8 + t);
        const float P  = __shfl_sync(0xffffffffu, v, 16 + t);
        const float S1 = __shfl_sync(0xffffffffu, v, 24);

        const float m    = S * (1.f / HDIM);
        const float var  = Q * (1.f / HDIM) - m * m;
        const float rstd = rsqrtf(var + LN_EPS);

        float logit = (lane >= 1 && lane < 8) ? rstd * (P - m * S1) : -1e30f;
        float mx = logit;
        mx = fmaxf(mx, __shfl_xor_sync(0xffffffffu, mx, 1));
        mx = fmaxf(mx, __shfl_xor_sync(0xffffffffu, mx, 2));
        mx = fmaxf(mx, __shfl_xor_sync(0xffffffffu, mx, 4));
        const float e = __expf(logit - mx);
        float se = e;
        se += __shfl_xor_sync(0xffffffffu, se, 1);
        se += __shfl_xor_sync(0xffffffffu, se, 2);
        se += __shfl_xor_sync(0xffffffffu, se, 4);
        const float a = e / se;

        const float k = (lane == 0) ? rstd : a * rstd;
        float Km = k * m;
        Km += __shfl_xor_sync(0xffffffffu, Km, 1);
        Km += __shfl_xor_sync(0xffffffffu, Km, 2);
        Km += __shfl_xor_sync(0xffffffffu, Km, 4);

        if (lane < 8) s_k[0][lane] = k;
        if (lane == 0) s_K[0] = Km;
    }
    __syncthreads();

    // ---- row 0 combine + store ---------------------------------------------
    {
        const float Kc = s_K[0];
        float2 acc = make_float2(0.f, 0.f);
        #pragma unroll
        for (int t = 0; t < SEQ; t++) {
            const float k = s_k[0][t];
            acc.x += k * xv0[t].x;
            acc.y += k * xv0[t].y;
        }
        const float2 bv = *reinterpret_cast<const float2*>(beta + col);
        const __half2 o = __floats2half2_rn(gv.x * (acc.x - Kc) + 2.f * bv.x,
                                            gv.y * (acc.y - Kc) + 2.f * bv.y);
        reinterpret_cast<__half2*>(g_fused)[row0 * (HDIM / 2) + tid] = o;
    }

    // ---- row 1 partials (loads long since landed) --------------------------
    #pragma unroll
    for (int t = 0; t < SEQ; t++) {
        const float2 v = xv1[t];
        vals[t]      = v.x + v.y;
        vals[8 + t]  = v.x * v.x + v.y * v.y;
        vals[16 + t] = gw.x * v.x + gw.y * v.y;
    }
    vals[24] = s1_local;
    #pragma unroll
    for (int j = 25; j < 32; j++) vals[j] = 0.f;

    #pragma unroll
    for (int bit = 16; bit >= 1; bit >>= 1) {
        #pragma unroll
        for (int j = 0; j < bit; j++) {
            const bool hi = (lane & bit) != 0;
            const float keep = hi ? vals[j + bit] : vals[j];
            const float send = hi ? vals[j] : vals[j + bit];
            vals[j] = keep + __shfl_xor_sync(0xffffffffu, send, bit);
        }
    }
    __syncthreads();   // s_red reuse: row-0 softmax reads are done
    if (lane < 25) s_red[w][lane] = vals[0];
    __syncthreads();

    if (w == 0) {
        float v = 0.f;
        if (lane < 25) {
            #pragma unroll
            for (int wi = 0; wi < 8; wi++) v += s_red[wi][lane];
        }
        const int t = lane & 7;
        const float S  = __shfl_sync(0xffffffffu, v, t);
        const float Q  = __shfl_sync(0xffffffffu, v, 8 + t);
        const float P  = __shfl_sync(0xffffffffu, v, 16 + t);
        const float S1 = __shfl_sync(0xffffffffu, v, 24);

        const float m    = S * (1.f / HDIM);
        const float var  = Q * (1.f / HDIM) - m * m;
        const float rstd = rsqrtf(var + LN_EPS);

        float logit = (lane >= 1 && lane < 8) ? rstd * (P - m * S1) : -1e30f;
        float mx = logit;
        mx = fmaxf(mx, __shfl_xor_sync(0xffffffffu, mx, 1));
        mx = fmaxf(mx, __shfl_xor_sync(0xffffffffu, mx, 2));
        mx = fmaxf(mx, __shfl_xor_sync(0xffffffffu, mx, 4));
        const float e = __expf(logit - mx);
        float se = e;
        se += __shfl_xor_sync(0xffffffffu, se, 1);
        se += __shfl_xor_sync(0xffffffffu, se, 2);
        se += __shfl_xor_sync(0xffffffffu, se, 4);
        const float a = e / se;

        const float k = (lane == 0) ? rstd : a * rstd;
        float Km = k * m;
        Km += __shfl_xor_sync(0xffffffffu, Km, 1);
        Km += __shfl_xor_sync(0xffffffffu, Km, 2);
        Km += __shfl_xor_sync(0xffffffffu, Km, 4);

        if (lane < 8) s_k[1][lane] = k;
        if (lane == 0) s_K[1] = Km;
    }
    __syncthreads();

    {
        const float Kc = s_K[1];
        float2 acc = make_float2(0.f, 0.f);
        #pragma unroll
        for (int t = 0; t < SEQ; t++) {
            const float k = s_k[1][t];
            acc.x += k * xv1[t].x;
            acc.y += k * xv1[t].y;
        }
        const float2 bv = *reinterpret_cast<const float2*>(beta + col);
        const __half2 o = __floats2half2_rn(gv.x * (acc.x - Kc) + 2.f * bv.x,
                                            gv.y * (acc.y - Kc) + 2.f * bv.y);
        reinterpret_cast<__half2*>(g_fused)[(row0 + 1) * (HDIM / 2) + tid] = o;
    }
}

// ---------------------------------------------------------------------------
// Transpose out_W [512,256] -> g_Bt [256,512] fp16.
// ---------------------------------------------------------------------------
__global__ __launch_bounds__(256) void transpose_B_kernel(const float* __restrict__ B) {
    __shared__ float tile[32][33];
    const int n0 = blockIdx.x * 32;
    const int k0 = blockIdx.y * 32;
    const int tx = threadIdx.x & 31;
    const int ty = threadIdx.x >> 5;
    #pragma unroll
    for (int i = 0; i < 32; i += 8)
        tile[ty + i][tx] = B[(size_t)(k0 + ty + i) * HOUT + n0 + tx];
    __syncthreads();
    #pragma unroll
    for (int i = 0; i < 32; i += 8) {
        g_Bt[(size_t)(n0 + ty + i) * HDIM + k0 + tx] = __float2half_rn(tile[tx][ty + i]);
    }
}

// ---------------------------------------------------------------------------
// Kernel B (v8): fp16 mma.sync GEMM — frozen from R16 (tensor-floor bound).
// ---------------------------------------------------------------------------
#define BM 128
#define BN 128
#define BKH 32
#define STAGES 3
#define A_STAGE_BYTES (BM * BKH * 2)
#define GEMM_SMEM     (STAGES * A_STAGE_BYTES)
#define NCH           (HDIM / BKH)

__global__ __launch_bounds__(256, 2) void gemm_v8_kernel(
    const float* __restrict__ bias,
    float* __restrict__ C)
{
    extern __shared__ char smem[];

    const int tid  = threadIdx.x;
    const int lane = tid & 31;
    const int wid  = tid >> 5;
    const int warp_m = wid & 3;
    const int warp_n = wid >> 2;
    const int g  = lane >> 2;
    const int tg = lane & 3;

    const int bn = blockIdx.x;
    const int bm = (int)(gridDim.y - 1) - (int)blockIdx.y;

    const __half* Ag = g_fused + (size_t)bm * BM * HDIM;
    const __half* Bg = g_Bt + (size_t)bn * BN * HDIM;

    const uint32_t smem_base = smem_u32(smem);

    const int st_row = tid >> 1;
    const int st_u   = (tid & 1) * 2;

    float acc[2][8][4];
    #pragma unroll
    for (int mt = 0; mt < 2; mt++)
        #pragma unroll
        for (int nt = 0; nt < 8; nt++)
            #pragma unroll
            for (int i = 0; i < 4; i++) acc[mt][nt][i] = 0.f;

    auto stage_A = [&](int kchunk, int st) {
        const uint32_t sA = smem_base + (uint32_t)(st * A_STAGE_BYTES);
        const __half* srcA = Ag + (size_t)st_row * HDIM + kchunk * BKH + st_u * 8;
        #pragma unroll
        for (int j = 0; j < 2; j++)
            cp_async16(sA + (uint32_t)(st_row * 4 + st_u + j) * 16u, srcA + j * 8);
    };

    stage_A(0, 0); CP_COMMIT();
    stage_A(1, 1); CP_COMMIT();

    #pragma unroll
    for (int k = 0; k < NCH; k++) {
        const int cur = k % STAGES;

        uint32_t bw0[4][4];
        #pragma unroll
        for (int q = 0; q < 4; q++) {
            const int n = warp_n * 64 + q * 8 + g;
            const uint4 v = *reinterpret_cast<const uint4*>(
                Bg + (size_t)n * HDIM + k * BKH + tg * 8);
            bw0[q][0] = v.x; bw0[q][1] = v.y; bw0[q][2] = v.z; bw0[q][3] = v.w;
        }

        CP_WAIT(1);
        __syncthreads();

        if (k + 2 < NCH) stage_A(k + 2, (k + 2) % STAGES);
        CP_COMMIT();

        const char* Abuf = smem + cur * A_STAGE_BYTES;

        uint32_t aw[2][2][4];
        #pragma unroll
        for (int mt = 0; mt < 2; mt++) {
            #pragma unroll
            for (int h = 0; h < 2; h++) {
                const int r = warp_m * 32 + mt * 16 + g + h * 8;
                const uint4 v = *reinterpret_cast<const uint4*>(
                    Abuf + (r * 4 + tg) * 16);
                aw[mt][h][0] = v.x; aw[mt][h][1] = v.y;
                aw[mt][h][2] = v.z; aw[mt][h][3] = v.w;
            }
        }

        uint32_t bw1[4][4];
        #pragma unroll
        for (int q = 0; q < 4; q++) {
            const int n = warp_n * 64 + (4 + q) * 8 + g;
            const uint4 v = *reinterpret_cast<const uint4*>(
                Bg + (size_t)n * HDIM + k * BKH + tg * 8);
            bw1[q][0] = v.x; bw1[q][1] = v.y; bw1[q][2] = v.z; bw1[q][3] = v.w;
        }

        #pragma unroll
        for (int grp = 0; grp < 2; grp++) {
            #pragma unroll
            for (int mt = 0; mt < 2; mt++) {
                #pragma unroll
                for (int q = 0; q < 4; q++) {
                    uint32_t a[4] = { aw[mt][0][grp * 2 + 0],
                                      aw[mt][1][grp * 2 + 0],
                                      aw[mt][0][grp * 2 + 1],
                                      aw[mt][1][grp * 2 + 1] };
                    uint32_t b[2] = { bw0[q][grp * 2 + 0],
                                      bw0[q][grp * 2 + 1] };
                    mma_fp16(acc[mt][q], a, b);
                }
            }
        }
        #pragma unroll
        for (int grp = 0; grp < 2; grp++) {
            #pragma unroll
            for (int mt = 0; mt < 2; mt++) {
                #pragma unroll
                for (int q = 0; q < 4; q++) {
                    uint32_t a[4] = { aw[mt][0][grp * 2 + 0],
                                      aw[mt][1][grp * 2 + 0],
                                      aw[mt][0][grp * 2 + 1],
                                      aw[mt][1][grp * 2 + 1] };
                    uint32_t b[2] = { bw1[q][grp * 2 + 0],
                                      bw1[q][grp * 2 + 1] };
                    mma_fp16(acc[mt][4 + q], a, b);
                }
            }
        }
    }

    const int row_base = bm * BM + warp_m * 32;
    const int col_base = bn * BN + warp_n * 64;
    #pragma unroll
    for (int mt = 0; mt < 2; mt++) {
        #pragma unroll
        for (int nt = 0; nt < 8; nt++) {
            const int r0 = row_base + mt * 16 + g;
            const int c0 = col_base + nt * 8 + 2 * tg;
            const float2 bb = *reinterpret_cast<const float2*>(bias + c0);
            float2 o0, o1;
            o0.x = fmaxf(acc[mt][nt][0] + bb.x, 0.f);
            o0.y = fmaxf(acc[mt][nt][1] + bb.y, 0.f);
            o1.x = fmaxf(acc[mt][nt][2] + bb.x, 0.f);
            o1.y = fmaxf(acc[mt][nt][3] + bb.y, 0.f);
            *reinterpret_cast<float2*>(C + (size_t)r0 * HOUT + c0) = o0;
            *reinterpret_cast<float2*>(C + (size_t)(r0 + 8) * HOUT + c0) = o1;
        }
    }
}

// ---------------------------------------------------------------------------
extern "C" void kernel_launch(void* const* d_in, const int* in_sizes, int n_in,
                              void* d_out, int out_size) {
    const float* x     = (const float*)d_in[0];   // [N, 8, 512]
    const float* gamma = (const float*)d_in[1];   // [512]
    const float* beta  = (const float*)d_in[2];   // [512]
    const float* attnW = (const float*)d_in[3];   // [1024, 1]
    // d_in[4] = attn_b: cancels in softmax.
    const float* outW  = (const float*)d_in[5];   // [512, 256]
    const float* outb  = (const float*)d_in[6];   // [256]
    float* out = (float*)d_out;                   // [N, 256]

    const int n = in_sizes[0] / (SEQ * HDIM);

    cudaFuncSetAttribute(gemm_v8_kernel,
                         cudaFuncAttributeMaxDynamicSharedMemorySize, GEMM_SMEM);

    transpose_B_kernel<<<dim3(HOUT / 32, HDIM / 32), 256>>>(outW);
    ln_attn_v7_kernel<<<n / 2, 256>>>(x, gamma, beta, attnW);

    dim3 grid(HOUT / BN, n / BM);
    gemm_v8_kernel<<<grid, 256, GEMM_SMEM>>>(outb, out);
}